// round 11
// baseline (speedup 1.0000x reference)
#include <cuda_runtime.h>
#include <cuda_fp16.h>
#include <cstdint>

// ---------------- problem constants ----------------
#define M_TOK   256
#define K_IN    4096
#define N_OUT   11008
#define QZ_COLS 1376

// ---------------- scratch ----------------
__device__ __half g_xh[M_TOK * K_IN];         // [m][k] fp16 rn(x), k-permuted per 8

// ---------------- split x: fp32 -> fp16, permute k within 8 ----------------
__global__ __launch_bounds__(256) void split_x(const float* __restrict__ x)
{
    int t = blockIdx.x * 256 + threadIdx.x;          // 0..131071, 8 floats each
    const float4* x4 = (const float4*)x;
    float4 v0 = x4[(size_t)t * 2];
    float4 v1 = x4[(size_t)t * 2 + 1];
    float f[8] = {v0.x, v0.y, v0.z, v0.w, v1.x, v1.y, v1.z, v1.w};
    uint4 hi;
    uint32_t* hp = (uint32_t*)&hi;
#pragma unroll
    for (int p = 0; p < 4; p++) {
        __half2 hh = __halves2half2(__float2half_rn(f[p]), __float2half_rn(f[p + 4]));
        hp[p] = *(uint32_t*)&hh;
    }
    *(uint4*)(g_xh + (size_t)t * 8) = hi;
}

// ---------------- GEMM: fused dequant, CTA 64x64, 2 warps of 64x32, BK=32 ----------------
#define STAGES 3
#define ROWB   80                 // 64 data bytes (32 halves) + 16 pad
#define B_OFF  (64 * ROWB)        // 5120
#define STG_B  (128 * ROWB)       // 10240
#define SMEM_DYN (STAGES * STG_B) // 30720 -> 7 CTAs/SM
#define NBLK   128                // k-blocks of 32

__device__ __forceinline__ uint32_t s2u(const void* p) {
    uint32_t a;
    asm("{ .reg .u64 t; cvta.to.shared.u64 t, %1; cvt.u32.u64 %0, t; }" : "=r"(a) : "l"(p));
    return a;
}
__device__ __forceinline__ void cp16(uint32_t d, const void* s) {
    asm volatile("cp.async.cg.shared.global [%0], [%1], 16;" :: "r"(d), "l"(s));
}
__device__ __forceinline__ void ldsm4(uint32_t* r, uint32_t a) {
    asm volatile("ldmatrix.sync.aligned.m8n8.x4.shared.b16 {%0,%1,%2,%3}, [%4];"
                 : "=r"(r[0]), "=r"(r[1]), "=r"(r[2]), "=r"(r[3]) : "r"(a));
}
__device__ __forceinline__ void mma16816(float* c, const uint32_t* a, const uint32_t* b) {
    asm volatile("mma.sync.aligned.m16n8k16.row.col.f32.f16.f16.f32 "
                 "{%0,%1,%2,%3}, {%4,%5,%6,%7}, {%8,%9}, {%0,%1,%2,%3};"
                 : "+f"(c[0]), "+f"(c[1]), "+f"(c[2]), "+f"(c[3])
                 : "r"(a[0]), "r"(a[1]), "r"(a[2]), "r"(a[3]), "r"(b[0]), "r"(b[1]));
}

__global__ __launch_bounds__(64, 7)
void qlin_mma(const int* __restrict__ qweight,
              const int* __restrict__ qzeros,
              const float* __restrict__ scales,
              const float* __restrict__ bias,
              float* __restrict__ out)
{
    extern __shared__ char smem[];
    const uint32_t sb = s2u(smem);
    char* smem_p = smem;

    const int tid = threadIdx.x;        // 0..63
    const int l   = tid & 31;
    const int wid = tid >> 5;           // 2 warps: each owns m=64, n=32
    const int m0  = blockIdx.x * 64;    // m fastest -> 4 m-CTAs share qweight slice in L2
    const int n0  = blockIdx.y * 64;

    // ---- A fill (cp.async): thread = row tid, 4 chunks of 16B ----
    const __half* gA = g_xh + (size_t)(m0 + tid) * K_IN;
    const uint32_t dA = (uint32_t)(tid * ROWB);

    // ---- B fill (fused dequant): thread = column nl = tid, packs kr=0..3 ----
    const int n = n0 + tid;
    const int zshift = (n & 7) * 4;
    const int* qwp = qweight + n;
    const int* qzp = qzeros + (n >> 3);
    const float* scp = scales + n;

    uint32_t spk[4];
    __half2  szb = __half2half2(__float2half_rn(0.f));
    __half2  ssh = szb;

    auto ldB = [&](int b) {
        const int* q = qwp + (size_t)b * 4 * N_OUT;
#pragma unroll
        for (int kr = 0; kr < 4; kr++)
            spk[kr] = (uint32_t)q[(size_t)kr * N_OUT];
        int g = b >> 2;
        unsigned zp = (unsigned)qzp[(size_t)g * QZ_COLS];
        int z1 = (int)((zp >> zshift) & 0xF) + 1;
        unsigned zbu = 0x64006400u + (unsigned)((z1 << 16) | z1);
        szb = *(__half2*)&zbu;
        ssh = __half2half2(__float2half_rn(scp[(size_t)g * N_OUT]));
    };

    auto stB = [&](int st) {
        char* dst0 = smem_p + st * STG_B + B_OFF + tid * ROWB;
#pragma unroll
        for (int kr = 0; kr < 4; kr++) {
            unsigned p = spk[kr];
            uint4 o;
            uint32_t* op = (uint32_t*)&o;
#pragma unroll
            for (int q = 0; q < 4; q++) {
                unsigned t = (p >> (4 * q)) & 0x000F000Fu;   // nibbles (v_q, v_{q+4})
                unsigned hh = t | 0x64006400u;               // halves 1024+v
                __half2 r2 = __hmul2(__hsub2(*(__half2*)&hh, szb), ssh);
                op[q] = *(uint32_t*)&r2;
            }
            *(uint4*)(dst0 + kr * 16) = o;
        }
    };

    auto issueA = [&](int st, int b) {
        uint32_t base = sb + st * STG_B + dA;
        const __half* src = gA + b * 32;
#pragma unroll
        for (int ch = 0; ch < 4; ch++)
            cp16(base + ch * 16, src + ch * 8);
    };

    float acc[4][4][4];
#pragma unroll
    for (int mi = 0; mi < 4; mi++)
#pragma unroll
        for (int ni = 0; ni < 4; ni++)
#pragma unroll
            for (int q = 0; q < 4; q++) acc[mi][ni][q] = 0.f;

    // ---- prologue ----
    ldB(0); stB(0); issueA(0, 0);
    asm volatile("cp.async.commit_group;");
    ldB(1); stB(1); issueA(1, 1);
    asm volatile("cp.async.commit_group;");
    ldB(2);
    __syncthreads();

    // ldsm lane offsets (bytes, relative to stage base)
    const uint32_t aLane = (uint32_t)((l & 15) * ROWB + (l >> 4) * 16);
    const uint32_t bLane = (uint32_t)(B_OFF + (wid * 32 + (l >> 4) * 8 + (l & 7)) * ROWB
                                      + ((l >> 3) & 1) * 16);

    int stage = 0;
    for (int it = 0; it < NBLK; it++) {
        asm volatile("cp.async.wait_group 1;" ::: "memory");
        __syncthreads();

        {
            int nst = stage + 2; if (nst >= STAGES) nst -= STAGES;
            if (it + 2 < NBLK) {
                stB(nst);
                issueA(nst, it + 2);
            }
            asm volatile("cp.async.commit_group;");
            if (it + 3 < NBLK) ldB(it + 3);
        }

        const uint32_t base = sb + stage * STG_B;
#pragma unroll
        for (int kk = 0; kk < 2; kk++) {
            uint32_t Af[4][4], Bf[4][2];
#pragma unroll
            for (int mi = 0; mi < 4; mi++)
                ldsm4(Af[mi], base + aLane + mi * (16 * ROWB) + kk * 32);
#pragma unroll
            for (int bi = 0; bi < 2; bi++) {
                uint32_t t[4];
                ldsm4(t, base + bLane + bi * (16 * ROWB) + kk * 32);
                Bf[bi * 2][0] = t[0]; Bf[bi * 2][1] = t[1];
                Bf[bi * 2 + 1][0] = t[2]; Bf[bi * 2 + 1][1] = t[3];
            }
#pragma unroll
            for (int mi = 0; mi < 4; mi++)
#pragma unroll
                for (int ni = 0; ni < 4; ni++)
                    mma16816(acc[mi][ni], Af[mi], Bf[ni]);
        }
        if (++stage >= STAGES) stage = 0;
    }

    // epilogue: add bias, store
#pragma unroll
    for (int mi = 0; mi < 4; mi++) {
        int r0 = m0 + mi * 16 + (l >> 2);
#pragma unroll
        for (int ni = 0; ni < 4; ni++) {
            int col = n0 + wid * 32 + ni * 8 + ((l & 3) << 1);
            float b0 = bias[col], b1 = bias[col + 1];
            float2 v;
            v.x = acc[mi][ni][0] + b0;
            v.y = acc[mi][ni][1] + b1;
            *(float2*)&out[(size_t)r0 * N_OUT + col] = v;
            v.x = acc[mi][ni][2] + b0;
            v.y = acc[mi][ni][3] + b1;
            *(float2*)&out[(size_t)(r0 + 8) * N_OUT + col] = v;
        }
    }
}

// ---------------- launch ----------------
extern "C" void kernel_launch(void* const* d_in, const int* in_sizes, int n_in,
                              void* d_out, int out_size)
{
    const float* x       = (const float*)d_in[0];   // [256, 4096]
    const int*   qweight = (const int*)  d_in[1];   // [512, 11008]
    const int*   qzeros  = (const int*)  d_in[2];   // [32, 1376]
    const float* scales  = (const float*)d_in[3];   // [32, 11008]
    const float* bias    = (const float*)d_in[4];   // [11008]
    float*       out     = (float*)d_out;           // [256, 11008]

    static bool s_init = false;
    if (!s_init) {
        cudaFuncSetAttribute(qlin_mma, cudaFuncAttributeMaxDynamicSharedMemorySize, SMEM_DYN);
        s_init = true;
    }

    split_x<<<512, 256>>>(x);
    dim3 gm_grid(M_TOK / 64, N_OUT / 64);           // (4, 172) = 688 tiles, m fastest
    qlin_mma<<<gm_grid, 64, SMEM_DYN>>>(qweight, qzeros, scales, bias, out);
}

// round 13
// speedup vs baseline: 1.3210x; 1.3210x over previous
#include <cuda_runtime.h>
#include <cuda_fp16.h>
#include <cstdint>

// ---------------- problem constants ----------------
#define M_TOK   256
#define K_IN    4096
#define N_OUT   11008
#define QZ_COLS 1376

// ---------------- scratch ----------------
__device__ __half g_xh[M_TOK * K_IN];         // [m][k] fp16 rn(x), k-permuted per 8

// ---------------- split x: fp32 -> fp16, permute k within 8 ----------------
// positions (2p, 2p+1) hold original (f[p], f[p+4])
__global__ __launch_bounds__(256) void split_x(const float* __restrict__ x)
{
    int t = blockIdx.x * 256 + threadIdx.x;          // 0..131071, 8 floats each
    const float4* x4 = (const float4*)x;
    float4 v0 = x4[(size_t)t * 2];
    float4 v1 = x4[(size_t)t * 2 + 1];
    float f[8] = {v0.x, v0.y, v0.z, v0.w, v1.x, v1.y, v1.z, v1.w};
    uint4 hi;
    uint32_t* hp = (uint32_t*)&hi;
#pragma unroll
    for (int p = 0; p < 4; p++) {
        __half2 hh = __halves2half2(__float2half_rn(f[p]), __float2half_rn(f[p + 4]));
        hp[p] = *(uint32_t*)&hh;
    }
    *(uint4*)(g_xh + (size_t)t * 8) = hi;
}

// ---------------- GEMM: reg-dequant B, CTA 64x64, 4 warps 32x32, BK=32 ----------------
#define STAGES  3
#define ROWB    80                    // A row: 64 data bytes + 16 pad
#define A_BYTES (64 * ROWB)           // 5120 per stage
#define BP_OFF  (STAGES * A_BYTES)    // 15360: packed-B region
#define BP_STG  1024                  // 64 cols x 4 krows x 4B, transposed [col][krow]
#define ZS_OFF  (BP_OFF + STAGES * BP_STG)   // 18432: wz2 table [32 g][64 c] u32
#define S2_OFF  (ZS_OFF + 8192)              // 26624: s2  table [32 g][64 c] u32
#define SMEM_DYN (S2_OFF + 8192)             // 34816 -> 4 CTAs/SM
#define NBLK    128

__device__ __forceinline__ uint32_t s2u(const void* p) {
    uint32_t a;
    asm("{ .reg .u64 t; cvta.to.shared.u64 t, %1; cvt.u32.u64 %0, t; }" : "=r"(a) : "l"(p));
    return a;
}
__device__ __forceinline__ void cp16(uint32_t d, const void* s) {
    asm volatile("cp.async.cg.shared.global [%0], [%1], 16;" :: "r"(d), "l"(s));
}
__device__ __forceinline__ void cp4(uint32_t d, const void* s) {
    asm volatile("cp.async.ca.shared.global [%0], [%1], 4;" :: "r"(d), "l"(s));
}
__device__ __forceinline__ void ldsm4(uint32_t* r, uint32_t a) {
    asm volatile("ldmatrix.sync.aligned.m8n8.x4.shared.b16 {%0,%1,%2,%3}, [%4];"
                 : "=r"(r[0]), "=r"(r[1]), "=r"(r[2]), "=r"(r[3]) : "r"(a));
}
__device__ __forceinline__ void mma16816(float* c, const uint32_t* a, const uint32_t* b) {
    asm volatile("mma.sync.aligned.m16n8k16.row.col.f32.f16.f16.f32 "
                 "{%0,%1,%2,%3}, {%4,%5,%6,%7}, {%8,%9}, {%0,%1,%2,%3};"
                 : "+f"(c[0]), "+f"(c[1]), "+f"(c[2]), "+f"(c[3])
                 : "r"(a[0]), "r"(a[1]), "r"(a[2]), "r"(a[3]), "r"(b[0]), "r"(b[1]));
}

__global__ __launch_bounds__(128, 4)
void qlin_mma(const int* __restrict__ qweight,
              const int* __restrict__ qzeros,
              const float* __restrict__ scales,
              const float* __restrict__ bias,
              float* __restrict__ out)
{
    extern __shared__ char smem[];
    const uint32_t sb = s2u(smem);
    char* smem_p = smem;

    const int tid = threadIdx.x;
    const int l   = tid & 31;
    const int wid = tid >> 5;
    const int wm  = wid & 1;            // 2 warps along m
    const int wn  = wid >> 1;           // 2 warps along n
    const int m0  = blockIdx.x * 64;    // m fastest -> qweight slice L2-shared
    const int n0  = blockIdx.y * 64;

    // ---- build zero/scale tables: wz2[g][c], s2[g][c] ----
    {
        uint32_t* zt = (uint32_t*)(smem_p + ZS_OFF);
        uint32_t* st = (uint32_t*)(smem_p + S2_OFF);
#pragma unroll
        for (int i = 0; i < 16; i++) {
            int idx = tid + i * 128;            // 0..2047
            int g = idx >> 6, c = idx & 63;
            int n = n0 + c;
            unsigned zp = (unsigned)qzeros[(size_t)g * QZ_COLS + (n >> 3)];
            int z1 = (int)((zp >> ((n & 7) * 4)) & 0xF) + 1;
            zt[idx] = 0x64006400u + (unsigned)z1 * 0x00010001u;
            __half2 s2 = __half2half2(__float2half_rn(scales[(size_t)g * N_OUT + n]));
            st[idx] = *(uint32_t*)&s2;
        }
    }

    // ---- A fill: thread covers rows (tid>>2), (tid>>2)+32, chunk (tid&3) ----
    const int arow = tid >> 2;
    const int fch  = (tid & 3) * 16;
    const __half* gA0 = g_xh + (size_t)(m0 + arow) * K_IN + fch / 2;
    const __half* gA1 = g_xh + (size_t)(m0 + arow + 32) * K_IN + fch / 2;
    const uint32_t dA0 = (uint32_t)(arow * ROWB + fch);
    const uint32_t dA1 = dA0 + 32 * ROWB;

    // ---- B pack fill: thread = (krow bkr = tid>>5, cols bc, bc+32) ----
    const int bkr = tid >> 5;
    const int bc  = tid & 31;
    const int* gQ0 = qweight + (size_t)bkr * N_OUT + n0 + bc;        // + b*4*N_OUT
    const int* gQ1 = gQ0 + 32;
    const uint32_t dBP0 = (uint32_t)(BP_OFF + bc * 16 + bkr * 4);
    const uint32_t dBP1 = dBP0 + 32 * 16;

    auto issue = [&](int st, int b) {
        uint32_t base = sb + st * A_BYTES;
        int k0 = b * 32;
        cp16(base + dA0, gA0 + k0);
        cp16(base + dA1, gA1 + k0);
        size_t qoff = (size_t)b * 4 * N_OUT;
        cp4(sb + dBP0 + st * BP_STG, gQ0 + qoff);
        cp4(sb + dBP1 + st * BP_STG, gQ1 + qoff);
        asm volatile("cp.async.commit_group;");
    };

    float acc[2][4][4];
#pragma unroll
    for (int mi = 0; mi < 2; mi++)
#pragma unroll
        for (int ni = 0; ni < 4; ni++)
#pragma unroll
            for (int q = 0; q < 4; q++) acc[mi][ni][q] = 0.f;

    issue(0, 0);
    issue(1, 1);
    __syncthreads();   // also covers the zs tables

    // ldsm/lane constants
    const uint32_t aLane = (uint32_t)((wm * 32 + (l & 15)) * ROWB + (l >> 4) * 16);
    const int cl  = wn * 32 + (l >> 2);        // base column for this lane's B frags
    const int sh  = (l & 3) * 4;               // nibble-pair shift

    const uint32_t* zt = (const uint32_t*)(smem_p + ZS_OFF);
    const uint32_t* st = (const uint32_t*)(smem_p + S2_OFF);

    uint32_t wz[4], sc[4];

    int stage = 0;
    for (int it = 0; it < NBLK; it++) {
        asm volatile("cp.async.wait_group 1;" ::: "memory");
        __syncthreads();
        {
            int nst = stage + 2; if (nst >= STAGES) nst -= STAGES;
            if (it + 2 < NBLK) issue(nst, it + 2);
            else asm volatile("cp.async.commit_group;");
        }

        if ((it & 3) == 0) {                   // new group of 128 k
            int g = it >> 2;
#pragma unroll
            for (int ni = 0; ni < 4; ni++) {
                wz[ni] = zt[g * 64 + cl + ni * 8];
                sc[ni] = st[g * 64 + cl + ni * 8];
            }
        }

        // load this iter's packs: 4 krows per column, transposed -> one LDS.128 per ni
        uint4 upk[4];
        {
            const char* bp = smem_p + BP_OFF + stage * BP_STG;
#pragma unroll
            for (int ni = 0; ni < 4; ni++)
                upk[ni] = *(const uint4*)(bp + (cl + ni * 8) * 16);
        }

        const uint32_t base = sb + stage * A_BYTES;
#pragma unroll
        for (int kk = 0; kk < 2; kk++) {
            uint32_t Af[2][4];
#pragma unroll
            for (int mi = 0; mi < 2; mi++)
                ldsm4(Af[mi], base + aLane + mi * (16 * ROWB) + kk * 32);

#pragma unroll
            for (int ni = 0; ni < 4; ni++) {
                uint32_t p0 = kk ? upk[ni].z : upk[ni].x;
                uint32_t p1 = kk ? upk[ni].w : upk[ni].y;
                uint32_t w0 = ((p0 >> sh) & 0x000F000Fu) | 0x64006400u;
                uint32_t w1 = ((p1 >> sh) & 0x000F000Fu) | 0x64006400u;
                __half2 zb = *(__half2*)&wz[ni];
                __half2 s2 = *(__half2*)&sc[ni];
                __half2 h0 = __hmul2(__hsub2(*(__half2*)&w0, zb), s2);
                __half2 h1 = __hmul2(__hsub2(*(__half2*)&w1, zb), s2);
                uint32_t B2[2] = { *(uint32_t*)&h0, *(uint32_t*)&h1 };
#pragma unroll
                for (int mi = 0; mi < 2; mi++)
                    mma16816(acc[mi][ni], Af[mi], B2);
            }
        }
        if (++stage >= STAGES) stage = 0;
    }

    // ---- epilogue: add bias, store ----
#pragma unroll
    for (int mi = 0; mi < 2; mi++) {
        int r0 = m0 + wm * 32 + mi * 16 + (l >> 2);
#pragma unroll
        for (int ni = 0; ni < 4; ni++) {
            int col = n0 + wn * 32 + ni * 8 + ((l & 3) << 1);
            float b0 = bias[col], b1 = bias[col + 1];
            float2 v;
            v.x = acc[mi][ni][0] + b0;
            v.y = acc[mi][ni][1] + b1;
            *(float2*)&out[(size_t)r0 * N_OUT + col] = v;
            v.x = acc[mi][ni][2] + b0;
            v.y = acc[mi][ni][3] + b1;
            *(float2*)&out[(size_t)(r0 + 8) * N_OUT + col] = v;
        }
    }
}

// ---------------- launch ----------------
extern "C" void kernel_launch(void* const* d_in, const int* in_sizes, int n_in,
                              void* d_out, int out_size)
{
    const float* x       = (const float*)d_in[0];   // [256, 4096]
    const int*   qweight = (const int*)  d_in[1];   // [512, 11008]
    const int*   qzeros  = (const int*)  d_in[2];   // [32, 1376]
    const float* scales  = (const float*)d_in[3];   // [32, 11008]
    const float* bias    = (const float*)d_in[4];   // [11008]
    float*       out     = (float*)d_out;           // [256, 11008]

    static bool s_init = false;
    if (!s_init) {
        cudaFuncSetAttribute(qlin_mma, cudaFuncAttributeMaxDynamicSharedMemorySize, SMEM_DYN);
        s_init = true;
    }

    split_x<<<512, 256>>>(x);
    dim3 gm_grid(M_TOK / 64, N_OUT / 64);           // (4, 172) = 688 tiles, m fastest
    qlin_mma<<<gm_grid, 128, SMEM_DYN>>>(qweight, qzeros, scales, bias, out);
}